// round 13
// baseline (speedup 1.0000x reference)
#include <cuda_runtime.h>
#include <cstdint>

#define TSTEPS 15
__device__ float g_dp[2048 * 4096];
__device__ float g_part[4 * 2048 * 128];

typedef unsigned long long u64;
__device__ __forceinline__ u64 pk(float lo, float hi) {
    u64 d; asm("mov.b64 %0,{%1,%2};" : "=l"(d) : "f"(lo), "f"(hi)); return d;
}
__device__ __forceinline__ void upk(u64 v, float& lo, float& hi) {
    asm("mov.b64 {%0,%1},%2;" : "=f"(lo), "=f"(hi) : "l"(v));
}
__device__ __forceinline__ u64 pku(uint32_t lo, uint32_t hi) {
    u64 d; asm("mov.b64 %0,{%1,%2};" : "=l"(d) : "r"(lo), "r"(hi)); return d;
}
__device__ __forceinline__ void upku(u64 v, uint32_t& lo, uint32_t& hi) {
    asm("mov.b64 {%0,%1},%2;" : "=r"(lo), "=r"(hi) : "l"(v));
}
__device__ __forceinline__ u64 f2(u64 a, u64 b, u64 c) {
    u64 d; asm("fma.rn.f32x2 %0,%1,%2,%3;" : "=l"(d) : "l"(a), "l"(b), "l"(c)); return d;
}
__device__ __forceinline__ u64 add2(u64 a, u64 b) {
    u64 d; asm("add.rn.f32x2 %0,%1,%2;" : "=l"(d) : "l"(a), "l"(b)); return d;
}
__device__ __forceinline__ void lds2(u64& a, u64& b, uint32_t addr) {
    asm volatile("ld.shared.v2.u64 {%0,%1},[%2];" : "=l"(a), "=l"(b) : "r"(addr));
}
__device__ __forceinline__ u64 lds1(uint32_t addr) {
    u64 a; asm volatile("ld.shared.b64 %0,[%1];" : "=l"(a) : "r"(addr)); return a;
}
__device__ __forceinline__ void sts2(uint32_t addr, u64 a, u64 b) {
    asm volatile("st.shared.v2.u64 [%0],{%1,%2};" :: "r"(addr), "l"(a), "l"(b));
}
__device__ __forceinline__ float lif_step(float& m, float cur, float beta, float thr) {
    float r = (m > thr) ? thr : 0.f;
    m = beta * m + (cur - r);
    return (m > thr) ? 1.f : 0.f;
}

// smem float offsets
#define SM_LT    0        // 64x64 Lt[m][n]
#define SM_PT_0  4096     // 32x64 Pt slot 0 (epilogue: A1t)
#define SM_PT_1  6144
#define SM_PT_2  8192
#define SM_WG2   10240    // 32x64 Wg2 plain (epilogue: Ws2 plain)
#define SM_ST    12288    // 16x64
#define SM_XS    13312    // 15x64
#define SM_ROWL  14272
#define SM_AX    14336
#define SM_P1    14400
#define SM_Q1    14432
#define SM_BG1   14464
#define SM_PS1   14496
#define SM_CS1   14528
#define SM_P2    14560
#define SM_Q2    14624
#define SM_BG2   14688
#define SM_PS2   14752
#define SM_QS2   14816
#define SM_COEF  14880    // 16
// bf16 s1 buffers (byte offsets): 3 x (64 rows x 32 cols x 2B) = 3 x 4096
#define SM_S1B0_B  59584
#define SM_S1B1_B  63680
#define SM_S1B2_B  67776
#define SM_TOTAL_B 71872

__global__ void __launch_bounds__(256, 1)
main_kernel(const float* __restrict__ L, const float* __restrict__ X,
            const float* __restrict__ Wproj, const float* __restrict__ bproj,
            const float* __restrict__ Wg1, const float* __restrict__ bg1,
            const float* __restrict__ Ws1, const float* __restrict__ bs1,
            const float* __restrict__ Wg2, const float* __restrict__ bg2,
            const float* __restrict__ Ws2, const float* __restrict__ bs2) {
    extern __shared__ float sm[];
    unsigned short* sm16 = (unsigned short*)sm;
    const uint32_t smb = (uint32_t)__cvta_generic_to_shared(sm);
    float* Lt = sm + SM_LT; float* Xs = sm + SM_XS; float* St = sm + SM_ST;
    float* rowL = sm + SM_ROWL; float* axs = sm + SM_AX; float* coef = sm + SM_COEF;

    const int tid = threadIdx.x;
    const int b = blockIdx.x;
    const float* Lb = L + (size_t)b * 4096;
    const float* Xb = X + (size_t)b * (TSTEPS * 64);

    {   // Lt transpose
        int n = tid >> 2, m0 = (tid & 3) * 16;
        #pragma unroll
        for (int q = 0; q < 4; q++) {
            float4 v = *(const float4*)(Lb + n * 64 + m0 + q * 4);
            Lt[(m0 + q * 4 + 0) * 64 + n] = v.x;
            Lt[(m0 + q * 4 + 1) * 64 + n] = v.y;
            Lt[(m0 + q * 4 + 2) * 64 + n] = v.z;
            Lt[(m0 + q * 4 + 3) * 64 + n] = v.w;
        }
    }
    for (int i = tid; i < TSTEPS * 64; i += 256) Xs[i] = Xb[i];
    #pragma unroll
    for (int k = 0; k < 8; k++)            // Wg2 plain
        sm[SM_WG2 + tid + k * 256] = Wg2[tid + k * 256];
    if (tid < 32) {                        // stage A derived consts
        float p1 = 0.f, q1 = 0.f, ps1 = 0.f, cs1 = 0.f;
        #pragma unroll
        for (int k = 0; k < 16; k++) {
            p1  += Wproj[k] * Wg1[k * 32 + tid];
            q1  += bproj[k] * Wg1[k * 32 + tid];
            ps1 += Wproj[k] * Ws1[k * 32 + tid];
            cs1 += bproj[k] * Ws1[k * 32 + tid];
        }
        cs1 += bs1[tid];
        sm[SM_P1 + tid] = p1; sm[SM_Q1 + tid] = q1;
        sm[SM_PS1 + tid] = ps1; sm[SM_CS1 + tid] = cs1;
        sm[SM_BG1 + tid] = bg1[tid];
    }
    if (tid == 32) {                       // coef
        float pw[TSTEPS]; pw[0] = 1.f;
        for (int k = 1; k < TSTEPS; k++) pw[k] = pw[k - 1] * 0.9f;
        float cs = 0.f;
        for (int tau = 0; tau < TSTEPS; tau++) {
            float late = 0.f, early = 0.f;
            for (int s = 10; s < 15; s++) if (s >= tau) late += pw[s - tau];
            for (int s = 0; s < 5; s++) if (s >= tau) early += pw[s - tau];
            float c = 0.2f * (late - early);
            coef[tau] = c; cs += c;
        }
        coef[15] = cs;
    }
    __syncthreads();

    if (tid < 64) {                        // stage B derived consts
        float p2 = 0.f, q2 = 0.f, ps2 = 0.f, qs2 = 0.f;
        #pragma unroll
        for (int f = 0; f < 32; f++) {
            float a = sm[SM_PS1 + f], c = sm[SM_CS1 + f];
            p2 += a * Wg2[f * 64 + tid]; q2 += c * Wg2[f * 64 + tid];
            ps2 += a * Ws2[f * 64 + tid]; qs2 += c * Ws2[f * 64 + tid];
        }
        qs2 += bs2[tid];
        sm[SM_P2 + tid] = p2; sm[SM_Q2 + tid] = q2;
        sm[SM_BG2 + tid] = bg2[tid];
        sm[SM_PS2 + tid] = ps2; sm[SM_QS2 + tid] = qs2;
    }
    #pragma unroll
    for (int k = 0; k < 4; k++) {          // St + rowL
        int idx = tid + k * 256;
        int n = idx & 63, tt = idx >> 6;
        float acc = 0.f;
        if (tt < TSTEPS) {
            const float* xr = Xs + tt * 64;
            #pragma unroll 8
            for (int m = 0; m < 64; m++) acc += Lt[m * 64 + n] * xr[m];
            St[tt * 64 + n] = acc;
        } else {
            #pragma unroll 8
            for (int m = 0; m < 64; m++) acc += Lt[m * 64 + n];
            rowL[n] = acc;
        }
    }
    __syncthreads();

    // ---- thread mappings ----
    const int lane = tid & 31, wA = tid >> 5;
    const int nR = (wA & 1) * 32 + (lane & 7) * 4;       // phase3 row quad
    const int c0 = (wA >> 1) * 16 + (lane >> 3) * 4;     // phase3 col quad
    const int nq4 = (tid & 15) * 16;                     // phase2 n-quad byte off
    const int jq  = tid >> 4;                            // phase2 j-quad (tid<128)

    const float p1f = sm[SM_P1 + lane], q1f = sm[SM_Q1 + lane], bg1f = sm[SM_BG1 + lane];
    const u64 p1dup = pk(p1f, p1f);
    u64 base1p[4];
    #pragma unroll
    for (int i2 = 0; i2 < 4; i2++) {
        int n0 = wA * 8 + i2 * 2;
        base1p[i2] = pk(rowL[n0] * q1f + bg1f, rowL[n0 + 1] * q1f + bg1f);
    }
    float m1[3][8], a1[8];
    #pragma unroll
    for (int i = 0; i < 8; i++) { m1[0][i] = m1[1][i] = m1[2][i] = a1[i] = 0.f; }

    // phase3 hoists: p2 dup per col; rank-1 bases n-paired
    u64 p2d[4], base2np[2][4];
    #pragma unroll
    for (int c = 0; c < 4; c++) {
        float p2v = sm[SM_P2 + c0 + c];
        p2d[c] = pk(p2v, p2v);
        float q2v = sm[SM_Q2 + c0 + c], bgv = sm[SM_BG2 + c0 + c];
        #pragma unroll
        for (int np = 0; np < 2; np++)
            base2np[np][c] = pk(rowL[nR + 2 * np] * q2v + bgv,
                                rowL[nR + 2 * np + 1] * q2v + bgv);
    }
    float m2[3][16], a2[16];
    #pragma unroll
    for (int e = 0; e < 16; e++) { m2[0][e] = m2[1][e] = m2[2][e] = a2[e] = 0.f; }

    const uint32_t bPT[3] = { smb + SM_PT_0 * 4, smb + SM_PT_1 * 4, smb + SM_PT_2 * 4 };
    const uint32_t bS1B[3] = { smb + SM_S1B0_B, smb + SM_S1B1_B, smb + SM_S1B2_B };
    const uint32_t bST = smb + SM_ST * 4;
    const uint32_t wAddr = smb + SM_WG2 * 4 + c0 * 4;    // + f*256
    const uint32_t lA2 = smb + SM_LT * 4 + nq4;          // + m*256

    // phase1: bf16 stores (spike sums 0..3 are exact in bf16)
    #define PHASE1(T, S1W)                                                        \
    {                                                                             \
        const float ct1 = coef[(T)];                                              \
        const uint32_t stR = bST + (T) * 256;                                     \
        unsigned short* sw = sm16 + (S1W) / 2;                                    \
        _Pragma("unroll")                                                         \
        for (int i2 = 0; i2 < 4; i2++) {                                          \
            int n0 = wA * 8 + i2 * 2;                                             \
            u64 Sp = lds1(stR + n0 * 4);                                          \
            u64 curp = f2(Sp, p1dup, base1p[i2]);                                 \
            float c0_, c1_; upk(curp, c0_, c1_);                                  \
            _Pragma("unroll")                                                     \
            for (int h = 0; h < 2; h++) {                                         \
                float cur = h ? c1_ : c0_;                                        \
                int u = i2 * 2 + h;                                               \
                float s = 0.f;                                                    \
                s += lif_step(m1[0][u], cur, 0.80f, 0.8f);                        \
                s += lif_step(m1[1][u], cur, 0.90f, 1.0f);                        \
                s += lif_step(m1[2][u], cur, 0.95f, 1.5f);                        \
                a1[u] += ct1 * s;                                                 \
                sw[(n0 + h) * 32 + lane] =                                        \
                    (unsigned short)(__float_as_uint(s) >> 16);                   \
            }                                                                     \
        }                                                                         \
    }

    // ================= time loop: 5 groups of 3 steps =================
    for (int g = 0; g < 5; g++) {
        const int t0 = g * 3;
        PHASE1(t0 + 0, SM_S1B0_B);
        PHASE1(t0 + 1, SM_S1B1_B);
        PHASE1(t0 + 2, SM_S1B2_B);
        __syncthreads();

        // ---- phase 2 grouped: P_t = L @ s1_t; L dup'd, s bf16 j-paired ----
        if (tid < 128) {
            u64 A[3][2][4];
            #pragma unroll
            for (int tt = 0; tt < 3; tt++)
                #pragma unroll
                for (int jp = 0; jp < 2; jp++)
                    #pragma unroll
                    for (int n = 0; n < 4; n++) A[tt][jp][n] = 0;
            #pragma unroll 4
            for (int m = 0; m < 64; m++) {
                u64 l01, l23;
                lds2(l01, l23, lA2 + m * 256);
                float L0, L1, L2, L3;
                upk(l01, L0, L1); upk(l23, L2, L3);
                u64 dL0 = pk(L0, L0), dL1 = pk(L1, L1);
                u64 dL2 = pk(L2, L2), dL3 = pk(L3, L3);
                #pragma unroll
                for (int tt = 0; tt < 3; tt++) {
                    u64 sv = lds1(bS1B[tt] + m * 64 + jq * 8);
                    uint32_t lo, hi; upku(sv, lo, hi);
                    u64 sp0 = pku(lo << 16, lo & 0xFFFF0000u);
                    u64 sp1 = pku(hi << 16, hi & 0xFFFF0000u);
                    A[tt][0][0] = f2(dL0, sp0, A[tt][0][0]);
                    A[tt][0][1] = f2(dL1, sp0, A[tt][0][1]);
                    A[tt][0][2] = f2(dL2, sp0, A[tt][0][2]);
                    A[tt][0][3] = f2(dL3, sp0, A[tt][0][3]);
                    A[tt][1][0] = f2(dL0, sp1, A[tt][1][0]);
                    A[tt][1][1] = f2(dL1, sp1, A[tt][1][1]);
                    A[tt][1][2] = f2(dL2, sp1, A[tt][1][2]);
                    A[tt][1][3] = f2(dL3, sp1, A[tt][1][3]);
                }
            }
            #pragma unroll
            for (int tt = 0; tt < 3; tt++)
                #pragma unroll
                for (int jp = 0; jp < 2; jp++) {
                    float l0, h0, l1, h1, l2, h2, l3, h3;
                    upk(A[tt][jp][0], l0, h0); upk(A[tt][jp][1], l1, h1);
                    upk(A[tt][jp][2], l2, h2); upk(A[tt][jp][3], l3, h3);
                    int jc = jq * 4 + jp * 2;
                    sts2(bPT[tt] + (jc + 0) * 256 + nq4, pk(l0, l1), pk(l2, l3));
                    sts2(bPT[tt] + (jc + 1) * 256 + nq4, pk(h0, h1), pk(h2, h3));
                }
        }
        __syncthreads();

        // ---- phase 3 grouped: cur2_t = P_t @ Wg2 + rank-1; n-paired accs ----
        {
            u64 C[3][2][4];
            #pragma unroll
            for (int tt = 0; tt < 3; tt++)
                #pragma unroll
                for (int np = 0; np < 2; np++)
                    #pragma unroll
                    for (int c = 0; c < 4; c++) C[tt][np][c] = 0;
            #pragma unroll 4
            for (int f = 0; f < 32; f++) {
                u64 w01, w23;
                lds2(w01, w23, wAddr + f * 256);
                float W0, W1, W2, W3;
                upk(w01, W0, W1); upk(w23, W2, W3);
                u64 dW0 = pk(W0, W0), dW1 = pk(W1, W1);
                u64 dW2 = pk(W2, W2), dW3 = pk(W3, W3);
                #pragma unroll
                for (int tt = 0; tt < 3; tt++) {
                    u64 p01, p23;
                    lds2(p01, p23, bPT[tt] + nR * 4 + f * 256);
                    C[tt][0][0] = f2(p01, dW0, C[tt][0][0]);
                    C[tt][0][1] = f2(p01, dW1, C[tt][0][1]);
                    C[tt][0][2] = f2(p01, dW2, C[tt][0][2]);
                    C[tt][0][3] = f2(p01, dW3, C[tt][0][3]);
                    C[tt][1][0] = f2(p23, dW0, C[tt][1][0]);
                    C[tt][1][1] = f2(p23, dW1, C[tt][1][1]);
                    C[tt][1][2] = f2(p23, dW2, C[tt][1][2]);
                    C[tt][1][3] = f2(p23, dW3, C[tt][1][3]);
                }
            }
            #pragma unroll
            for (int tt = 0; tt < 3; tt++) {
                const int t = t0 + tt;
                const float ct = coef[t];
                u64 sc01, sc23;
                lds2(sc01, sc23, bST + t * 256 + nR * 4);
                #pragma unroll
                for (int np = 0; np < 2; np++) {
                    u64 scp = np ? sc23 : sc01;
                    #pragma unroll
                    for (int c = 0; c < 4; c++) {
                        u64 curp = f2(scp, p2d[c], add2(C[tt][np][c], base2np[np][c]));
                        float cl, ch; upk(curp, cl, ch);
                        #pragma unroll
                        for (int h = 0; h < 2; h++) {
                            float cur = h ? ch : cl;
                            int e = (np * 2 + h) * 4 + c;   // (local row)*4 + c
                            float s = 0.f;
                            s += lif_step(m2[0][e], cur, 0.80f, 0.8f);
                            s += lif_step(m2[1][e], cur, 0.90f, 1.0f);
                            s += lif_step(m2[2][e], cur, 0.95f, 1.5f);
                            a2[e] += ct * s;
                        }
                    }
                }
            }
        }
    }
    __syncthreads();

    // ======================= epilogue =======================
    #pragma unroll
    for (int i = 0; i < 8; i++)                  // A1t[f][n] into PT_0
        sm[SM_PT_0 + lane * 64 + wA * 8 + i] = a1[i];
    #pragma unroll
    for (int k = 0; k < 8; k++)                  // Ws2 plain over Wg2 region
        sm[SM_WG2 + tid + k * 256] = Ws2[tid + k * 256];
    if (tid < 64) {                              // ax[n]
        float acc = 0.f;
        #pragma unroll
        for (int t = 0; t < TSTEPS; t++) acc += coef[t] * Xs[t * 64 + tid];
        axs[tid] = acc;
    }
    __syncthreads();

    u64 D[2][4];
    #pragma unroll
    for (int np = 0; np < 2; np++)
        #pragma unroll
        for (int c = 0; c < 4; c++)
            D[np][c] = pk(a2[(np * 2) * 4 + c], a2[(np * 2 + 1) * 4 + c]);

    const uint32_t pA0 = bPT[0] + nR * 4;
    #pragma unroll
    for (int f = 0; f < 32; f++) {               // + acc1 @ Ws2 (n-paired)
        u64 w01, w23;
        lds2(w01, w23, wAddr + f * 256);
        float W0, W1, W2, W3;
        upk(w01, W0, W1); upk(w23, W2, W3);
        u64 dW0 = pk(W0, W0), dW1 = pk(W1, W1);
        u64 dW2 = pk(W2, W2), dW3 = pk(W3, W3);
        u64 p01, p23;
        lds2(p01, p23, pA0 + f * 256);
        D[0][0] = f2(p01, dW0, D[0][0]);  D[0][1] = f2(p01, dW1, D[0][1]);
        D[0][2] = f2(p01, dW2, D[0][2]);  D[0][3] = f2(p01, dW3, D[0][3]);
        D[1][0] = f2(p23, dW0, D[1][0]);  D[1][1] = f2(p23, dW1, D[1][1]);
        D[1][2] = f2(p23, dW2, D[1][2]);  D[1][3] = f2(p23, dW3, D[1][3]);
    }
    const float csum = coef[15];
    float ps2c[4], qs2c[4];
    #pragma unroll
    for (int c = 0; c < 4; c++) {
        ps2c[c] = sm[SM_PS2 + c0 + c];
        qs2c[c] = sm[SM_QS2 + c0 + c];
    }
    #pragma unroll
    for (int np = 0; np < 2; np++) {
        float vl[4], vh[4];
        #pragma unroll
        for (int c = 0; c < 4; c++) upk(D[np][c], vl[c], vh[c]);
        #pragma unroll
        for (int h = 0; h < 2; h++) {
            int n = nR + np * 2 + h;
            float axv = axs[n];
            float* v = h ? vh : vl;
            float4 o;
            o.x = v[0] + axv * ps2c[0] + csum * qs2c[0];
            o.y = v[1] + axv * ps2c[1] + csum * qs2c[1];
            o.z = v[2] + axv * ps2c[2] + csum * qs2c[2];
            o.w = v[3] + axv * ps2c[3] + csum * qs2c[3];
            *(float4*)(g_dp + (size_t)b * 4096 + n * 64 + c0) = o;
        }
    }
    #undef PHASE1
}

// ---------------------------------------------------------------------------
__global__ void __launch_bounds__(256)
decoder_partial(const float* __restrict__ Wc1, float* __restrict__ part) {
    __shared__ float Wc1s[64 * 128];
    __shared__ float dpT[64 * 16];

    const int tid = threadIdx.x;
    const int b0 = blockIdx.x * 16;
    const int ks = blockIdx.y;
    const int kbase = ks * 1024;

    const int j = tid & 127, rh = tid >> 7;
    const uint32_t bDP = (uint32_t)__cvta_generic_to_shared(dpT);
    u64 hp[4];
    #pragma unroll
    for (int r = 0; r < 4; r++) hp[r] = 0;

    for (int k0 = kbase; k0 < kbase + 1024; k0 += 64) {
        __syncthreads();
        #pragma unroll
        for (int p = 0; p < 8; p++) {
            int f4 = tid + p * 256;
            int kk = f4 >> 5, jq = f4 & 31;
            *(float4*)(Wc1s + kk * 128 + jq * 4) =
                *(const float4*)(Wc1 + (size_t)(k0 + kk) * 128 + jq * 4);
        }
        {
            int r = tid >> 4, kq = tid & 15;
            float4 v = *(const float4*)(g_dp + (size_t)(b0 + r) * 4096 + k0 + kq * 4);
            dpT[(kq * 4 + 0) * 16 + r] = v.x;
            dpT[(kq * 4 + 1) * 16 + r] = v.y;
            dpT[(kq * 4 + 2) * 16 + r] = v.z;
            dpT[(kq * 4 + 3) * 16 + r] = v.w;
        }
        __syncthreads();
        #pragma unroll 8
        for (int kk = 0; kk < 64; kk++) {
            float w = Wc1s[kk * 128 + j];
            u64 wd = pk(w, w);
            u64 d0, d1, d2, d3;
            lds2(d0, d1, bDP + kk * 64 + rh * 32);
            lds2(d2, d3, bDP + kk * 64 + rh * 32 + 16);
            hp[0] = f2(d0, wd, hp[0]);
            hp[1] = f2(d1, wd, hp[1]);
            hp[2] = f2(d2, wd, hp[2]);
            hp[3] = f2(d3, wd, hp[3]);
        }
    }
    #pragma unroll
    for (int r = 0; r < 4; r++) {
        float lo, hi; upk(hp[r], lo, hi);
        int row0 = rh * 8 + r * 2;
        part[((size_t)ks * 2048 + (b0 + row0 + 0)) * 128 + j] = lo;
        part[((size_t)ks * 2048 + (b0 + row0 + 1)) * 128 + j] = hi;
    }
}

__global__ void __launch_bounds__(256)
decoder_finish(const float* __restrict__ part, const float* __restrict__ bc1,
               const float* __restrict__ Wc2, const float* __restrict__ bc2,
               float* __restrict__ out) {
    __shared__ float hs[16 * 128];
    __shared__ float Wc2s[128 * 4];

    const int tid = threadIdx.x;
    const int b0 = blockIdx.x * 16;
    for (int i = tid; i < 512; i += 256) Wc2s[i] = Wc2[i];

    const int j = tid & 127, rh = tid >> 7;
    const float bb = bc1[j];
    #pragma unroll
    for (int r = 0; r < 8; r++) {
        int row = rh * 8 + r;
        size_t off = (size_t)(b0 + row) * 128 + j;
        float v = part[off] + part[(size_t)2048 * 128 + off]
                + part[(size_t)2 * 2048 * 128 + off]
                + part[(size_t)3 * 2048 * 128 + off] + bb;
        hs[row * 128 + j] = v > 0.f ? v : 0.f;
    }
    __syncthreads();
    if (tid < 64) {
        int r = tid >> 2, c = tid & 3;
        float acc = bc2[c];
        #pragma unroll 8
        for (int jj = 0; jj < 128; jj++) acc += hs[r * 128 + jj] * Wc2s[jj * 4 + c];
        out[(b0 + r) * 4 + c] = acc;
    }
}

// ---------------------------------------------------------------------------
extern "C" void kernel_launch(void* const* d_in, const int* in_sizes, int n_in,
                              void* d_out, int out_size) {
    const float* L     = (const float*)d_in[0];
    const float* X     = (const float*)d_in[1];
    const float* Wproj = (const float*)d_in[2];
    const float* bproj = (const float*)d_in[3];
    const float* Wg1   = (const float*)d_in[4];
    const float* bg1   = (const float*)d_in[5];
    const float* Ws1   = (const float*)d_in[6];
    const float* bs1   = (const float*)d_in[7];
    const float* Wg2   = (const float*)d_in[8];
    const float* bg2   = (const float*)d_in[9];
    const float* Ws2   = (const float*)d_in[10];
    const float* bs2   = (const float*)d_in[11];
    const float* Wc1   = (const float*)d_in[12];
    const float* bc1   = (const float*)d_in[13];
    const float* Wc2   = (const float*)d_in[14];
    const float* bc2   = (const float*)d_in[15];
    float* out = (float*)d_out;

    int B = in_sizes[0] / 4096;
    if (B > 2048) B = 2048;

    cudaFuncSetAttribute(main_kernel, cudaFuncAttributeMaxDynamicSharedMemorySize,
                         SM_TOTAL_B);

    float* part;
    cudaGetSymbolAddress((void**)&part, g_part);

    main_kernel<<<B, 256, SM_TOTAL_B>>>(L, X, Wproj, bproj, Wg1, bg1, Ws1, bs1,
                                        Wg2, bg2, Ws2, bs2);
    dim3 gridA(B / 16, 4);
    decoder_partial<<<gridA, 256>>>(Wc1, part);
    decoder_finish<<<B / 16, 256>>>(part, bc1, Wc2, bc2, out);
}